// round 12
// baseline (speedup 1.0000x reference)
#include <cuda_runtime.h>
#include <math.h>

#define NB 256      // batch
#define NS 196      // seq
#define ND 1024     // dim
#define NP 512      // pool
#define NL 8        // length
#define TOPK 4
#define SSPLIT 7
#define SCHUNK 28   // 196/7

// GEMM config
#define TM 64
#define TN 128
#define GKC 32
#define SPLITK 8
#define KSLICE (ND / SPLITK)   // 128
#define ARS 132                // As2 row stride (floats)
#define BRS 132                // Bs row stride (floats), plain layout

// K1 fused grid partition
#define K1_MEAN NB                      // 256 full-mean blocks
#define K1_KEY  (K1_MEAN + NP)          // +512 key-norm blocks
#define NGUM    (TOPK * NB * NP)        // 524288 gumbel values
#define K1_GUM  (K1_KEY + NGUM / 1024)  // +512 gumbel blocks (256 thr x 4)

// ---------------- scratch (no allocations allowed) ----------------
__device__ float g_q[NB * ND];                   // mean query (un-normalized)
__device__ float g_qs[NB];                       // 1/||q|| per batch
__device__ float g_ks[NP];                       // 1/||k|| per pool row
__device__ float g_simp[SPLITK * NB * NP];       // split-K raw-dot partials
__device__ float g_gum[NGUM];                    // precomputed gumbel noise

// packed dual-fp32 FMA (sm_100+): bitwise-identical to two scalar FFMAs
__device__ __forceinline__ unsigned long long ffma2(unsigned long long a,
                                                    unsigned long long b,
                                                    unsigned long long c) {
    unsigned long long d;
    asm("fma.rn.f32x2 %0, %1, %2, %3;" : "=l"(d) : "l"(a), "l"(b), "l"(c));
    return d;
}

__device__ __forceinline__ float gumbelf(float u) {
    float t = -logf(u + 1e-10f);
    return -logf(t + 1e-10f);
}

// ---------------- K1: full mean+qnorm / key norms / gumbel precompute -----
// Mean path reproduces the old two-kernel accumulation order exactly:
// per 28-chunk even/odd a0/a1 sums, chunks combined sequentially sp=0..6,
// then /196 and the 256-wide smem tree reduce -> bit-identical g_q, g_qs.
__global__ void k1_fused(const float* __restrict__ x,
                         const float* __restrict__ key,
                         const float* __restrict__ gum) {
    int blk = blockIdx.x, tid = threadIdx.x;
    if (blk < K1_MEAN) {
        __shared__ float red[256];
        int b = blk;
        float4 acc;
#pragma unroll 1
        for (int sp = 0; sp < SSPLIT; ++sp) {
            const float4* xp = (const float4*)x
                + (size_t)(b * NS + sp * SCHUNK) * (ND / 4) + tid;
            float4 a0 = make_float4(0.f, 0.f, 0.f, 0.f);
            float4 a1 = make_float4(0.f, 0.f, 0.f, 0.f);
#pragma unroll 14
            for (int s = 0; s < SCHUNK; s += 2) {
                float4 v0 = __ldcs(&xp[(size_t)s * (ND / 4)]);
                float4 v1 = __ldcs(&xp[(size_t)(s + 1) * (ND / 4)]);
                a0.x += v0.x; a0.y += v0.y; a0.z += v0.z; a0.w += v0.w;
                a1.x += v1.x; a1.y += v1.y; a1.z += v1.z; a1.w += v1.w;
            }
            a0.x += a1.x; a0.y += a1.y; a0.z += a1.z; a0.w += a1.w;
            if (sp == 0) acc = a0;
            else {
                acc.x += a0.x; acc.y += a0.y; acc.z += a0.z; acc.w += a0.w;
            }
        }
        float4 q;
        q.x = acc.x / (float)NS; q.y = acc.y / (float)NS;
        q.z = acc.z / (float)NS; q.w = acc.w / (float)NS;
        ((float4*)g_q)[b * (ND / 4) + tid] = q;
        red[tid] = q.x * q.x + q.y * q.y + q.z * q.z + q.w * q.w;
        __syncthreads();
        for (int s = 128; s > 0; s >>= 1) {
            if (tid < s) red[tid] += red[tid + s];
            __syncthreads();
        }
        if (tid == 0) g_qs[b] = rsqrtf(fmaxf(red[0], 1e-12f));
    } else if (blk < K1_KEY) {
        __shared__ float red[256];
        int kp = blk - K1_MEAN;
        float4 v = ((const float4*)key)[kp * (ND / 4) + tid];
        red[tid] = v.x * v.x + v.y * v.y + v.z * v.z + v.w * v.w;
        __syncthreads();
        for (int s = 128; s > 0; s >>= 1) {
            if (tid < s) red[tid] += red[tid + s];
            __syncthreads();
        }
        if (tid == 0) g_ks[kp] = rsqrtf(fmaxf(red[0], 1e-12f));
    } else {
        int base = (blk - K1_KEY) * 1024 + tid;
#pragma unroll
        for (int j = 0; j < 4; ++j) {
            int idx = base + j * 256;
            g_gum[idx] = gumbelf(gum[idx]);
        }
    }
}

// ---------------- K2: raw dots = g_q @ key^T (split-K, FFMA2) -------------
// 64x128 tile, 256 threads (8 warps as 4x2, lanes as 4x8), 4 rows x 8 cols
// per thread. Per-lane B columns {wn*64+lc*4..+3} and {+32..+35}: LDS.64
// reads hit 8 distinct bank pairs -> conflict-free, no skew.
__global__ void k_gemm(const float* __restrict__ key) {
    __shared__ __align__(16) float As2[GKC][ARS];   // [k][2*m] duplicated
    __shared__ __align__(16) float Bs[GKC][BRS];    // [k][n] plain
    int tid = threadIdx.x;
    int n0 = blockIdx.x * TN, m0 = blockIdx.y * TM, ks = blockIdx.z;
    int k0 = ks * KSLICE;

    int w = tid >> 5, lane = tid & 31;
    int wm = w & 3, wn = w >> 2;
    int lr = lane >> 3, lc = lane & 7;
    int aoff = 2 * (wm * 16 + lr * 4);
    int c0 = wn * 64 + lc * 4;
    int c1 = c0 + 32;

    int am = tid >> 3;          // 0..31
    int kq = tid & 7;           // float4 within 32-k chunk

    const float4* Ag = (const float4*)g_q;
    const float4* Bg = (const float4*)key;

    unsigned long long acc[4][4];
#pragma unroll
    for (int i = 0; i < 4; ++i)
#pragma unroll
        for (int j = 0; j < 4; ++j) acc[i][j] = 0ULL;

    int kb = (k0 >> 2) + kq;
    float4 pa0 = Ag[(m0 + am) * (ND / 4) + kb];
    float4 pa1 = Ag[(m0 + am + 32) * (ND / 4) + kb];
    float4 pb0 = Bg[(n0 + am) * (ND / 4) + kb];
    float4 pb1 = Bg[(n0 + am + 32) * (ND / 4) + kb];
    float4 pb2 = Bg[(n0 + am + 64) * (ND / 4) + kb];
    float4 pb3 = Bg[(n0 + am + 96) * (ND / 4) + kb];

    for (int kt = 0; kt < KSLICE; kt += GKC) {
        __syncthreads();
        int kk = kq * 4;
        *(float2*)&As2[kk + 0][2 * am] = make_float2(pa0.x, pa0.x);
        *(float2*)&As2[kk + 1][2 * am] = make_float2(pa0.y, pa0.y);
        *(float2*)&As2[kk + 2][2 * am] = make_float2(pa0.z, pa0.z);
        *(float2*)&As2[kk + 3][2 * am] = make_float2(pa0.w, pa0.w);
        *(float2*)&As2[kk + 0][2 * (am + 32)] = make_float2(pa1.x, pa1.x);
        *(float2*)&As2[kk + 1][2 * (am + 32)] = make_float2(pa1.y, pa1.y);
        *(float2*)&As2[kk + 2][2 * (am + 32)] = make_float2(pa1.z, pa1.z);
        *(float2*)&As2[kk + 3][2 * (am + 32)] = make_float2(pa1.w, pa1.w);
        Bs[kk + 0][am]      = pb0.x; Bs[kk + 1][am]      = pb0.y;
        Bs[kk + 2][am]      = pb0.z; Bs[kk + 3][am]      = pb0.w;
        Bs[kk + 0][am + 32] = pb1.x; Bs[kk + 1][am + 32] = pb1.y;
        Bs[kk + 2][am + 32] = pb1.z; Bs[kk + 3][am + 32] = pb1.w;
        Bs[kk + 0][am + 64] = pb2.x; Bs[kk + 1][am + 64] = pb2.y;
        Bs[kk + 2][am + 64] = pb2.z; Bs[kk + 3][am + 64] = pb2.w;
        Bs[kk + 0][am + 96] = pb3.x; Bs[kk + 1][am + 96] = pb3.y;
        Bs[kk + 2][am + 96] = pb3.z; Bs[kk + 3][am + 96] = pb3.w;
        __syncthreads();
        if (kt + GKC < KSLICE) {
            int kb2 = ((k0 + kt + GKC) >> 2) + kq;
            pa0 = Ag[(m0 + am) * (ND / 4) + kb2];
            pa1 = Ag[(m0 + am + 32) * (ND / 4) + kb2];
            pb0 = Bg[(n0 + am) * (ND / 4) + kb2];
            pb1 = Bg[(n0 + am + 32) * (ND / 4) + kb2];
            pb2 = Bg[(n0 + am + 64) * (ND / 4) + kb2];
            pb3 = Bg[(n0 + am + 96) * (ND / 4) + kb2];
        }
#pragma unroll
        for (int k = 0; k < GKC; ++k) {
            unsigned long long a0 = *(const unsigned long long*)&As2[k][aoff + 0];
            unsigned long long a1 = *(const unsigned long long*)&As2[k][aoff + 2];
            unsigned long long a2 = *(const unsigned long long*)&As2[k][aoff + 4];
            unsigned long long a3 = *(const unsigned long long*)&As2[k][aoff + 6];
            unsigned long long b0 = *(const unsigned long long*)&Bs[k][c0 + 0];
            unsigned long long b1 = *(const unsigned long long*)&Bs[k][c0 + 2];
            unsigned long long b2 = *(const unsigned long long*)&Bs[k][c1 + 0];
            unsigned long long b3 = *(const unsigned long long*)&Bs[k][c1 + 2];
            acc[0][0] = ffma2(a0, b0, acc[0][0]); acc[0][1] = ffma2(a0, b1, acc[0][1]);
            acc[0][2] = ffma2(a0, b2, acc[0][2]); acc[0][3] = ffma2(a0, b3, acc[0][3]);
            acc[1][0] = ffma2(a1, b0, acc[1][0]); acc[1][1] = ffma2(a1, b1, acc[1][1]);
            acc[1][2] = ffma2(a1, b2, acc[1][2]); acc[1][3] = ffma2(a1, b3, acc[1][3]);
            acc[2][0] = ffma2(a2, b0, acc[2][0]); acc[2][1] = ffma2(a2, b1, acc[2][1]);
            acc[2][2] = ffma2(a2, b2, acc[2][2]); acc[2][3] = ffma2(a2, b3, acc[2][3]);
            acc[3][0] = ffma2(a3, b0, acc[3][0]); acc[3][1] = ffma2(a3, b1, acc[3][1]);
            acc[3][2] = ffma2(a3, b2, acc[3][2]); acc[3][3] = ffma2(a3, b3, acc[3][3]);
        }
    }
    int mt = wm * 16 + lr * 4;
#pragma unroll
    for (int i = 0; i < 4; ++i) {
        float2 v0 = *(float2*)&acc[i][0];
        float2 v1 = *(float2*)&acc[i][1];
        float2 v2 = *(float2*)&acc[i][2];
        float2 v3 = *(float2*)&acc[i][3];
        size_t rb = ((size_t)ks * NB + m0 + mt + i) * NP + n0;
        *(float4*)&g_simp[rb + c0] = make_float4(v0.x, v0.y, v1.x, v1.y);
        *(float4*)&g_simp[rb + c1] = make_float4(v2.x, v2.y, v3.x, v3.y);
    }
}

// ---------------- K3: selection with software-pipelined gather (R8) -------
__global__ void k_select_gather(const float* __restrict__ prompt,
                                float* __restrict__ out) {
    __shared__ float wval[16];
    __shared__ int   widx[16];
    __shared__ int   best[TOPK];
    int b = blockIdx.x, p = threadIdx.x;
    int lane = p & 31, w = p >> 5;

    // reduce split-K partials, apply deferred normalization
    float cur = 0.f;
#pragma unroll
    for (int s = 0; s < SPLITK; ++s)
        cur += g_simp[((size_t)s * NB + b) * NP + p];
    cur *= g_qs[b] * g_ks[p];

    float g[TOPK];
#pragma unroll
    for (int i = 0; i < TOPK; ++i)
        g[i] = g_gum[((size_t)i * NB + b) * NP + p];

    float4* ob = (float4*)out + (size_t)b * TOPK * NL * (ND / 4);
    float4 rv[4];

    // sim in [-1,1], gumbel in [-3.2, 23.1] => a selected entry at -1000 can
    // never win again, so mask-out == index exclusion.
    for (int i = 0; i < TOPK; ++i) {
        bool excl = false;
#pragma unroll
        for (int j = 0; j < TOPK; ++j)
            if (j < i && best[j] == p) excl = true;
        float v = excl ? -1e30f : cur + g[i];
        int idx = p;
#pragma unroll
        for (int o = 16; o > 0; o >>= 1) {
            float ov = __shfl_down_sync(0xFFFFFFFFu, v, o);
            int   oi = __shfl_down_sync(0xFFFFFFFFu, idx, o);
            if (ov > v || (ov == v && oi < idx)) { v = ov; idx = oi; }
        }
        if (lane == 0) { wval[w] = v; widx[w] = idx; }
        __syncthreads();
        if (w == 0) {
            float v2 = wval[lane & 15];
            int   i2 = widx[lane & 15];
#pragma unroll
            for (int o = 8; o > 0; o >>= 1) {
                float ov = __shfl_down_sync(0xFFFFFFFFu, v2, o);
                int   oi = __shfl_down_sync(0xFFFFFFFFu, i2, o);
                if (ov > v2 || (ov == v2 && oi < i2)) { v2 = ov; i2 = oi; }
            }
            if (lane == 0) best[i] = i2;
        }
        __syncthreads();

        // pipeline: drain previous selection's registers, launch this one's loads
        int sel = best[i];
        if (i > 0) {
            float4* dst = ob + (i - 1) * NL * (ND / 4);
#pragma unroll
            for (int j = 0; j < 4; ++j)
                dst[p + 512 * j] = rv[j];
        }
        const float4* src = (const float4*)prompt + (size_t)sel * NL * (ND / 4);
#pragma unroll
        for (int j = 0; j < 4; ++j)
            rv[j] = src[p + 512 * j];
    }
    {
        float4* dst = ob + (TOPK - 1) * NL * (ND / 4);
#pragma unroll
        for (int j = 0; j < 4; ++j)
            dst[p + 512 * j] = rv[j];
    }
}

// ---------------- launch ----------------
extern "C" void kernel_launch(void* const* d_in, const int* in_sizes, int n_in,
                              void* d_out, int out_size) {
    const float* x      = (const float*)d_in[0];  // [256,196,1024]
    const float* prompt = (const float*)d_in[1];  // [512,8,1024]
    const float* key    = (const float*)d_in[2];  // [512,1024]
    const float* gum    = (const float*)d_in[3];  // [4,256,512]
    float* out          = (float*)d_out;          // [256,32,1024]

    k1_fused<<<K1_GUM, 256>>>(x, key, gum);
    k_gemm<<<dim3(NP / TN, NB / TM, SPLITK), 256>>>(key);
    k_select_gather<<<NB, NP>>>(prompt, out);
}

// round 13
// speedup vs baseline: 1.1438x; 1.1438x over previous
#include <cuda_runtime.h>
#include <math.h>

#define NB 256      // batch
#define NS 196      // seq
#define ND 1024     // dim
#define NP 512      // pool
#define NL 8        // length
#define TOPK 4
#define SSPLIT 7
#define SCHUNK 28   // 196/7

// GEMM config
#define TM 64
#define TN 128
#define GKC 32
#define SPLITK 8
#define KSLICE (ND / SPLITK)   // 128
#define ARS 132                // As2 row stride (floats)
#define BRS 132                // Bs row stride (floats), plain layout

// K1 fused grid partition
#define K1_PART (NB * SSPLIT)          // 1792 partial-mean blocks
#define K1_KEY  (K1_PART + NP)         // +512 key-norm blocks
#define NGUM    (TOPK * NB * NP)       // 524288 gumbel values
#define K1_GUM  (K1_KEY + NGUM / 1024) // +512 gumbel blocks (256 thr x 4)

// ---------------- scratch (no allocations allowed) ----------------
__device__ float g_part[SSPLIT * NB * ND];       // partial sums (7 MB)
__device__ float g_q[NB * ND];                   // mean query (un-normalized)
__device__ float g_qs[NB];                       // 1/||q|| per batch
__device__ float g_ks[NP];                       // 1/||k|| per pool row
__device__ float g_simp[SPLITK * NB * NP];       // split-K raw-dot partials
__device__ float g_gum[NGUM];                    // precomputed gumbel noise

// packed dual-fp32 FMA (sm_100+): bitwise-identical to two scalar FFMAs
__device__ __forceinline__ unsigned long long ffma2(unsigned long long a,
                                                    unsigned long long b,
                                                    unsigned long long c) {
    unsigned long long d;
    asm("fma.rn.f32x2 %0, %1, %2, %3;" : "=l"(d) : "l"(a), "l"(b), "l"(c));
    return d;
}

__device__ __forceinline__ float gumbelf(float u) {
    float t = -logf(u + 1e-10f);
    return -logf(t + 1e-10f);
}

// ---------------- K1: partial means + key norms + gumbel precompute -------
__global__ void k1_fused(const float* __restrict__ x,
                         const float* __restrict__ key,
                         const float* __restrict__ gum) {
    int blk = blockIdx.x, tid = threadIdx.x;
    if (blk < K1_PART) {
        int sp = blk / NB, b = blk - sp * NB;
        const float4* xp = (const float4*)x + (size_t)(b * NS + sp * SCHUNK) * (ND / 4) + tid;
        float4 a0 = make_float4(0.f, 0.f, 0.f, 0.f);
        float4 a1 = make_float4(0.f, 0.f, 0.f, 0.f);
#pragma unroll 14
        for (int s = 0; s < SCHUNK; s += 2) {
            float4 v0 = __ldcs(&xp[(size_t)s * (ND / 4)]);
            float4 v1 = __ldcs(&xp[(size_t)(s + 1) * (ND / 4)]);
            a0.x += v0.x; a0.y += v0.y; a0.z += v0.z; a0.w += v0.w;
            a1.x += v1.x; a1.y += v1.y; a1.z += v1.z; a1.w += v1.w;
        }
        a0.x += a1.x; a0.y += a1.y; a0.z += a1.z; a0.w += a1.w;
        ((float4*)g_part)[(sp * NB + b) * (ND / 4) + tid] = a0;
    } else if (blk < K1_KEY) {
        __shared__ float red[256];
        int kp = blk - K1_PART;
        float4 v = ((const float4*)key)[kp * (ND / 4) + tid];
        red[tid] = v.x * v.x + v.y * v.y + v.z * v.z + v.w * v.w;
        __syncthreads();
        for (int s = 128; s > 0; s >>= 1) {
            if (tid < s) red[tid] += red[tid + s];
            __syncthreads();
        }
        if (tid == 0) g_ks[kp] = rsqrtf(fmaxf(red[0], 1e-12f));
    } else {
        int base = (blk - K1_KEY) * 1024 + tid;
#pragma unroll
        for (int j = 0; j < 4; ++j) {
            int idx = base + j * 256;
            g_gum[idx] = gumbelf(gum[idx]);
        }
    }
}

// ---------------- K2: combine partials -> mean query + its inverse norm ---
__global__ void k_norms() {
    __shared__ float red[256];
    int blk = blockIdx.x, tid = threadIdx.x;
    const float4* pp = (const float4*)g_part;
    float4 acc = pp[(0 * NB + blk) * (ND / 4) + tid];
#pragma unroll
    for (int s = 1; s < SSPLIT; ++s) {
        float4 p = pp[(s * NB + blk) * (ND / 4) + tid];
        acc.x += p.x; acc.y += p.y; acc.z += p.z; acc.w += p.w;
    }
    float4 q;
    q.x = acc.x / (float)NS; q.y = acc.y / (float)NS;
    q.z = acc.z / (float)NS; q.w = acc.w / (float)NS;
    ((float4*)g_q)[blk * (ND / 4) + tid] = q;
    float ss = q.x * q.x + q.y * q.y + q.z * q.z + q.w * q.w;
    red[tid] = ss;
    __syncthreads();
    for (int s = 128; s > 0; s >>= 1) {
        if (tid < s) red[tid] += red[tid + s];
        __syncthreads();
    }
    if (tid == 0) g_qs[blk] = rsqrtf(fmaxf(red[0], 1e-12f));
}

// ---------------- K3: raw dots = g_q @ key^T (split-K, FFMA2) -------------
// 64x128 tile, 256 threads (8 warps as 4x2, lanes as 4x8), 4 rows x 8 cols
// per thread. Per-lane B columns {wn*64+lc*4..+3} and {+32..+35}: LDS.64
// reads hit 8 distinct bank pairs -> conflict-free, no skew.
__global__ void k_gemm(const float* __restrict__ key) {
    __shared__ __align__(16) float As2[GKC][ARS];   // [k][2*m] duplicated
    __shared__ __align__(16) float Bs[GKC][BRS];    // [k][n] plain
    int tid = threadIdx.x;
    int n0 = blockIdx.x * TN, m0 = blockIdx.y * TM, ks = blockIdx.z;
    int k0 = ks * KSLICE;

    int w = tid >> 5, lane = tid & 31;
    int wm = w & 3, wn = w >> 2;
    int lr = lane >> 3, lc = lane & 7;
    int aoff = 2 * (wm * 16 + lr * 4);
    int c0 = wn * 64 + lc * 4;
    int c1 = c0 + 32;

    int am = tid >> 3;          // 0..31
    int kq = tid & 7;           // float4 within 32-k chunk

    const float4* Ag = (const float4*)g_q;
    const float4* Bg = (const float4*)key;

    unsigned long long acc[4][4];
#pragma unroll
    for (int i = 0; i < 4; ++i)
#pragma unroll
        for (int j = 0; j < 4; ++j) acc[i][j] = 0ULL;

    int kb = (k0 >> 2) + kq;
    float4 pa0 = Ag[(m0 + am) * (ND / 4) + kb];
    float4 pa1 = Ag[(m0 + am + 32) * (ND / 4) + kb];
    float4 pb0 = Bg[(n0 + am) * (ND / 4) + kb];
    float4 pb1 = Bg[(n0 + am + 32) * (ND / 4) + kb];
    float4 pb2 = Bg[(n0 + am + 64) * (ND / 4) + kb];
    float4 pb3 = Bg[(n0 + am + 96) * (ND / 4) + kb];

    for (int kt = 0; kt < KSLICE; kt += GKC) {
        __syncthreads();
        int kk = kq * 4;
        *(float2*)&As2[kk + 0][2 * am] = make_float2(pa0.x, pa0.x);
        *(float2*)&As2[kk + 1][2 * am] = make_float2(pa0.y, pa0.y);
        *(float2*)&As2[kk + 2][2 * am] = make_float2(pa0.z, pa0.z);
        *(float2*)&As2[kk + 3][2 * am] = make_float2(pa0.w, pa0.w);
        *(float2*)&As2[kk + 0][2 * (am + 32)] = make_float2(pa1.x, pa1.x);
        *(float2*)&As2[kk + 1][2 * (am + 32)] = make_float2(pa1.y, pa1.y);
        *(float2*)&As2[kk + 2][2 * (am + 32)] = make_float2(pa1.z, pa1.z);
        *(float2*)&As2[kk + 3][2 * (am + 32)] = make_float2(pa1.w, pa1.w);
        Bs[kk + 0][am]      = pb0.x; Bs[kk + 1][am]      = pb0.y;
        Bs[kk + 2][am]      = pb0.z; Bs[kk + 3][am]      = pb0.w;
        Bs[kk + 0][am + 32] = pb1.x; Bs[kk + 1][am + 32] = pb1.y;
        Bs[kk + 2][am + 32] = pb1.z; Bs[kk + 3][am + 32] = pb1.w;
        Bs[kk + 0][am + 64] = pb2.x; Bs[kk + 1][am + 64] = pb2.y;
        Bs[kk + 2][am + 64] = pb2.z; Bs[kk + 3][am + 64] = pb2.w;
        Bs[kk + 0][am + 96] = pb3.x; Bs[kk + 1][am + 96] = pb3.y;
        Bs[kk + 2][am + 96] = pb3.z; Bs[kk + 3][am + 96] = pb3.w;
        __syncthreads();
        if (kt + GKC < KSLICE) {
            int kb2 = ((k0 + kt + GKC) >> 2) + kq;
            pa0 = Ag[(m0 + am) * (ND / 4) + kb2];
            pa1 = Ag[(m0 + am + 32) * (ND / 4) + kb2];
            pb0 = Bg[(n0 + am) * (ND / 4) + kb2];
            pb1 = Bg[(n0 + am + 32) * (ND / 4) + kb2];
            pb2 = Bg[(n0 + am + 64) * (ND / 4) + kb2];
            pb3 = Bg[(n0 + am + 96) * (ND / 4) + kb2];
        }
#pragma unroll
        for (int k = 0; k < GKC; ++k) {
            unsigned long long a0 = *(const unsigned long long*)&As2[k][aoff + 0];
            unsigned long long a1 = *(const unsigned long long*)&As2[k][aoff + 2];
            unsigned long long a2 = *(const unsigned long long*)&As2[k][aoff + 4];
            unsigned long long a3 = *(const unsigned long long*)&As2[k][aoff + 6];
            unsigned long long b0 = *(const unsigned long long*)&Bs[k][c0 + 0];
            unsigned long long b1 = *(const unsigned long long*)&Bs[k][c0 + 2];
            unsigned long long b2 = *(const unsigned long long*)&Bs[k][c1 + 0];
            unsigned long long b3 = *(const unsigned long long*)&Bs[k][c1 + 2];
            acc[0][0] = ffma2(a0, b0, acc[0][0]); acc[0][1] = ffma2(a0, b1, acc[0][1]);
            acc[0][2] = ffma2(a0, b2, acc[0][2]); acc[0][3] = ffma2(a0, b3, acc[0][3]);
            acc[1][0] = ffma2(a1, b0, acc[1][0]); acc[1][1] = ffma2(a1, b1, acc[1][1]);
            acc[1][2] = ffma2(a1, b2, acc[1][2]); acc[1][3] = ffma2(a1, b3, acc[1][3]);
            acc[2][0] = ffma2(a2, b0, acc[2][0]); acc[2][1] = ffma2(a2, b1, acc[2][1]);
            acc[2][2] = ffma2(a2, b2, acc[2][2]); acc[2][3] = ffma2(a2, b3, acc[2][3]);
            acc[3][0] = ffma2(a3, b0, acc[3][0]); acc[3][1] = ffma2(a3, b1, acc[3][1]);
            acc[3][2] = ffma2(a3, b2, acc[3][2]); acc[3][3] = ffma2(a3, b3, acc[3][3]);
        }
    }
    int mt = wm * 16 + lr * 4;
#pragma unroll
    for (int i = 0; i < 4; ++i) {
        float2 v0 = *(float2*)&acc[i][0];
        float2 v1 = *(float2*)&acc[i][1];
        float2 v2 = *(float2*)&acc[i][2];
        float2 v3 = *(float2*)&acc[i][3];
        size_t rb = ((size_t)ks * NB + m0 + mt + i) * NP + n0;
        *(float4*)&g_simp[rb + c0] = make_float4(v0.x, v0.y, v1.x, v1.y);
        *(float4*)&g_simp[rb + c1] = make_float4(v2.x, v2.y, v3.x, v3.y);
    }
}

// ---------------- K4: pipelined selection + half-split gather -------------
// Grid NB*2: block (b, h) runs the FULL selection with R8's two-phase
// reduction (bit-identical in both halves), but copies only half of each
// selection, software-pipelined across rounds.
__global__ void k_select_gather(const float* __restrict__ prompt,
                                float* __restrict__ out) {
    __shared__ float wval[16];
    __shared__ int   widx[16];
    __shared__ int   best[TOPK];
    int bb = blockIdx.x;
    int b = bb >> 1, h = bb & 1;
    int p = threadIdx.x;
    int lane = p & 31, w = p >> 5;

    // reduce split-K partials, apply deferred normalization
    float cur = 0.f;
#pragma unroll
    for (int s = 0; s < SPLITK; ++s)
        cur += g_simp[((size_t)s * NB + b) * NP + p];
    cur *= g_qs[b] * g_ks[p];

    float g[TOPK];
#pragma unroll
    for (int i = 0; i < TOPK; ++i)
        g[i] = g_gum[((size_t)i * NB + b) * NP + p];

    float4* ob = (float4*)out + (size_t)b * TOPK * NL * (ND / 4);
    int o0 = p + 512 * (2 * h);
    int o1 = p + 512 * (2 * h + 1);
    float4 rv0, rv1;

    // sim in [-1,1], gumbel in [-3.2, 23.1] => a selected entry at -1000 can
    // never win again, so mask-out == index exclusion.
    for (int i = 0; i < TOPK; ++i) {
        bool excl = false;
#pragma unroll
        for (int j = 0; j < TOPK; ++j)
            if (j < i && best[j] == p) excl = true;
        float v = excl ? -1e30f : cur + g[i];
        int idx = p;
#pragma unroll
        for (int o = 16; o > 0; o >>= 1) {
            float ov = __shfl_down_sync(0xFFFFFFFFu, v, o);
            int   oi = __shfl_down_sync(0xFFFFFFFFu, idx, o);
            if (ov > v || (ov == v && oi < idx)) { v = ov; idx = oi; }
        }
        if (lane == 0) { wval[w] = v; widx[w] = idx; }
        __syncthreads();
        if (w == 0) {
            float v2 = wval[lane & 15];
            int   i2 = widx[lane & 15];
#pragma unroll
            for (int o = 8; o > 0; o >>= 1) {
                float ov = __shfl_down_sync(0xFFFFFFFFu, v2, o);
                int   oi = __shfl_down_sync(0xFFFFFFFFu, i2, o);
                if (ov > v2 || (ov == v2 && oi < i2)) { v2 = ov; i2 = oi; }
            }
            if (lane == 0) best[i] = i2;
        }
        __syncthreads();

        // pipeline: drain previous selection's registers, launch this one's loads
        int sel = best[i];
        if (i > 0) {
            float4* dst = ob + (i - 1) * NL * (ND / 4);
            __stcs(&dst[o0], rv0);
            __stcs(&dst[o1], rv1);
        }
        const float4* src = (const float4*)prompt + (size_t)sel * NL * (ND / 4);
        rv0 = src[o0];
        rv1 = src[o1];
    }
    {
        float4* dst = ob + (TOPK - 1) * NL * (ND / 4);
        __stcs(&dst[o0], rv0);
        __stcs(&dst[o1], rv1);
    }
}

// ---------------- launch ----------------
extern "C" void kernel_launch(void* const* d_in, const int* in_sizes, int n_in,
                              void* d_out, int out_size) {
    const float* x      = (const float*)d_in[0];  // [256,196,1024]
    const float* prompt = (const float*)d_in[1];  // [512,8,1024]
    const float* key    = (const float*)d_in[2];  // [512,1024]
    const float* gum    = (const float*)d_in[3];  // [4,256,512]
    float* out          = (float*)d_out;          // [256,32,1024]

    k1_fused<<<K1_GUM, 256>>>(x, key, gum);
    k_norms<<<NB, 256>>>();
    k_gemm<<<dim3(NP / TN, NB / TM, SPLITK), 256>>>(key);
    k_select_gather<<<NB * 2, NP>>>(prompt, out);
}